// round 17
// baseline (speedup 1.0000x reference)
#include <cuda_runtime.h>
#include <cstdint>

// Flow1 via mma.sync m16n8k16 bf16 (3-product compensation), packed pre-split
// weights, m32 x n16 warp tiles at 2 CTAs/SM, group-counted cp.async staging.
// R17 = R15 + ldmatrix fragment loads (clean rebuild of R16): GEMM1-B,
// GEMM2-A(H), GEMM2-B fetched with ldmatrix.m8n8.x4; per-warp addresses
// computed once, per-chunk advance +32B. Epilogue z/bias access is float2.
// B=262144 rows, Z=128, ZH=64, HS=50 (padded 56), 4 couplings.
// Out: [ z (B*128) | logpz (B) | logqz (B) ] fp32.

#define ZZ 128
#define ZH 64
#define HS 50
#define NC 4
#define TPB 256
#define MR 64
#define PZ 72      // fp32 z pitch (floats); 72 % 32 = 8 -> conflict-free LDS.64
#define KPI 36     // k-pair pitch (words); rows start at bank 4r -> LDSM clean

// global packed-weight layout (per coupling), words
#define W0H 0                  // 56 n x 36 kp
#define W0L 2016
#define GW12 4032              // W1/W2 block
#define W1Hr 0
#define W1Lr 2304
#define W2Hr 4608
#define W2Lr 6912
#define WTOT 13248

// smem word offsets
#define OW0   0                // 4032
#define OW12  4032             // 9216
#define OB    13248            // 2 x 192 (bias double buffer)
#define OZ1   13632            // 64 x 72
#define OZ2   18240
#define OHH   22848            // 64 x 36
#define OHL   25152
#define OQ0   27456            // 64
#define OLD   27520            // 4 x 64
#define OSS   27776            // 4 x 64
#define SMEM_WORDS 28032
#define SMEM_BYTES (SMEM_WORDS * 4)    // 112128 -> 2 CTAs/SM

__device__ __align__(16) unsigned gW[NC][WTOT];
__device__ __align__(16) float gBB[NC][192];

__device__ __forceinline__ float tanh_fast(float x) {
    float r;
    asm("tanh.approx.f32 %0, %1;" : "=f"(r) : "f"(x));
    return r;
}
__device__ __forceinline__ unsigned pack2(float hi_elem, float lo_elem) {
    unsigned r;
    asm("cvt.rn.bf16x2.f32 %0, %1, %2;" : "=r"(r) : "f"(hi_elem), "f"(lo_elem));
    return r;
}
// split (x = even-k, y = odd-k) into packed hi word + packed lo word
__device__ __forceinline__ void split2(float x, float y, unsigned& h, unsigned& l) {
    h = pack2(y, x);
    float hx = __uint_as_float(h << 16);
    float hy = __uint_as_float(h & 0xFFFF0000u);
    l = pack2(y - hy, x - hx);
}
__device__ __forceinline__ void mma16(float (&d)[4], const unsigned* a,
                                      unsigned b0, unsigned b1) {
    asm volatile(
        "mma.sync.aligned.m16n8k16.row.col.f32.bf16.bf16.f32 "
        "{%0,%1,%2,%3}, {%4,%5,%6,%7}, {%8,%9}, {%0,%1,%2,%3};"
        : "+f"(d[0]), "+f"(d[1]), "+f"(d[2]), "+f"(d[3])
        : "r"(a[0]), "r"(a[1]), "r"(a[2]), "r"(a[3]), "r"(b0), "r"(b1));
}
__device__ __forceinline__ void ldsm4(unsigned& r0, unsigned& r1,
                                      unsigned& r2, unsigned& r3, unsigned addr) {
    asm volatile("ldmatrix.sync.aligned.m8n8.x4.shared.b16 {%0,%1,%2,%3}, [%4];"
                 : "=r"(r0), "=r"(r1), "=r"(r2), "=r"(r3) : "r"(addr));
}
__device__ __forceinline__ void cp16(void* sdst, const void* gsrc) {
    unsigned s = (unsigned)__cvta_generic_to_shared(sdst);
    asm volatile("cp.async.cg.shared.global [%0], [%1], 16;" :: "r"(s), "l"(gsrc));
}
#define CP_COMMIT() asm volatile("cp.async.commit_group;" ::: "memory")
#define CP_WAIT0()  asm volatile("cp.async.wait_group 0;" ::: "memory")
#define CP_WAIT1()  asm volatile("cp.async.wait_group 1;" ::: "memory")

// ---------------- pre-split kernel ----------------
__global__ void presplit_kernel(const float* __restrict__ W_in,  const float* __restrict__ b_in,
                                const float* __restrict__ W_mu,  const float* __restrict__ b_mu,
                                const float* __restrict__ W_sig, const float* __restrict__ b_sig)
{
    const int cc = blockIdx.x;
    const int tid = threadIdx.x;
    for (int idx = tid; idx < 56 * KPI; idx += blockDim.x) {
        int n = idx / KPI, kp = idx - n * KPI;
        int k0 = 2 * kp, k1 = k0 + 1;
        float v0 = (n < HS && k0 < ZH) ? W_in[cc * HS * ZH + n * ZH + k0] : 0.0f;
        float v1 = (n < HS && k1 < ZH) ? W_in[cc * HS * ZH + n * ZH + k1] : 0.0f;
        unsigned h, l;
        split2(v0, v1, h, l);
        gW[cc][W0H + idx] = h;
        gW[cc][W0L + idx] = l;
    }
    for (int idx = tid; idx < 64 * KPI; idx += blockDim.x) {
        int n = idx / KPI, kp = idx - n * KPI;
        int k0 = 2 * kp, k1 = k0 + 1;
        float m0 = (k0 < HS) ? W_mu [cc * ZH * HS + n * HS + k0] : 0.0f;
        float m1 = (k1 < HS) ? W_mu [cc * ZH * HS + n * HS + k1] : 0.0f;
        float s0 = (k0 < HS) ? W_sig[cc * ZH * HS + n * HS + k0] : 0.0f;
        float s1 = (k1 < HS) ? W_sig[cc * ZH * HS + n * HS + k1] : 0.0f;
        unsigned h, l;
        split2(m0, m1, h, l);
        gW[cc][GW12 + W1Hr + idx] = h;
        gW[cc][GW12 + W1Lr + idx] = l;
        split2(s0, s1, h, l);
        gW[cc][GW12 + W2Hr + idx] = h;
        gW[cc][GW12 + W2Lr + idx] = l;
    }
    if (tid < 64) {
        gBB[cc][tid]       = (tid < HS) ? b_in[cc * HS + tid] : 0.0f;
        gBB[cc][64 + tid]  = b_mu [cc * ZH + tid];
        gBB[cc][128 + tid] = b_sig[cc * ZH + tid];
    }
}

// ---------------- main kernel ----------------
__global__ void __launch_bounds__(TPB, 2)
flow_kernel(const float* __restrict__ mean,  const float* __restrict__ logvar,
            const float* __restrict__ eps,
            float* __restrict__ out, int Brows)
{
    extern __shared__ float sm[];
    float*    sZ1  = sm + OZ1;
    float*    sZ2  = sm + OZ2;
    unsigned* uHH  = (unsigned*)(sm + OHH);
    unsigned* uHL  = (unsigned*)(sm + OHL);
    float*    sQ0  = sm + OQ0;
    float*    sLD  = sm + OLD;
    float*    sSS  = sm + OSS;

    const int tid  = threadIdx.x;
    const int lane = tid & 31;
    const int wid  = tid >> 5;
    const int wm   = wid & 1;          // m-group: rows 32*wm..+31
    const int wn   = wid >> 1;         // n-quarter (0..3)
    const int gid  = lane >> 2;
    const int tig  = lane & 3;
    const int rb   = 32 * wm;
    const int rowBase = blockIdx.x * MR;
    const unsigned smemB = (unsigned)__cvta_generic_to_shared(sm);

    // ---- ldmatrix per-thread base addresses (constant across couplings) ----
    // B-type: matrices = {nn0,k0-3},{nn0,k4-7},{nn1,k0-3},{nn1,k4-7}
    //         lanes 8m..8m+7 give matrix-m row addresses
    const int bmrow = 8 * (2 * wn + ((lane >> 4) & 1)) + (lane & 7);
    const int bkofs = 4 * ((lane >> 3) & 1);
    const unsigned adrW0h = smemB + (unsigned)(OW0 + W0H + bmrow * KPI + bkofs) * 4u;
    const unsigned adrW0l = smemB + (unsigned)(OW0 + W0L + bmrow * KPI + bkofs) * 4u;
    const unsigned adrW1h = smemB + (unsigned)(OW12 + W1Hr + bmrow * KPI + bkofs) * 4u;
    const unsigned adrW1l = smemB + (unsigned)(OW12 + W1Lr + bmrow * KPI + bkofs) * 4u;
    const unsigned adrW2h = smemB + (unsigned)(OW12 + W2Hr + bmrow * KPI + bkofs) * 4u;
    const unsigned adrW2l = smemB + (unsigned)(OW12 + W2Lr + bmrow * KPI + bkofs) * 4u;
    // A-type (H): matrices = {r+0,k0-3},{r+8,k0-3},{r+0,k4-7},{r+8,k4-7}
    const int amrow0 = rb + (lane & 7) + 8 * ((lane >> 3) & 1);
    const int akofs  = 4 * ((lane >> 4) & 1);
    const unsigned adrAh0 = smemB + (unsigned)(OHH + amrow0 * KPI + akofs) * 4u;
    const unsigned adrAl0 = smemB + (unsigned)(OHL + amrow0 * KPI + akofs) * 4u;
    const unsigned adrAh1 = adrAh0 + 16u * KPI * 4u;   // s2=1: rows +16
    const unsigned adrAl1 = adrAl0 + 16u * KPI * 4u;

    // ---- prefetch coupling 0: group A = {W0,b}, group B = {W12} ----
    {
        const float4* s0 = (const float4*)(&gW[0][0]);
        float4* d0 = (float4*)(sm + OW0);
        for (int i = tid; i < 4032 / 4; i += TPB) cp16(d0 + i, s0 + i);
        if (tid < 48) cp16((float4*)(sm + OB) + tid, (const float4*)(&gBB[0][0]) + tid);
        CP_COMMIT();
        const float4* s1 = (const float4*)(&gW[0][GW12]);
        float4* d1 = (float4*)(sm + OW12);
        for (int i = tid; i < 9216 / 4; i += TPB) cp16(d1 + i, s1 + i);
        CP_COMMIT();
    }

    // ---- zero H k-pad (kp 28..31, 64 rows) ----
    if (tid < 256) {
        int r = tid >> 2, kp = 28 + (tid & 3);
        uHH[r * KPI + kp] = 0u;
        uHL[r * KPI + kp] = 0u;
    }

    // ================= reparam (4 threads/row) =================
    {
        const int rrow = tid >> 2, p = tid & 3;
        float part = 0.0f;
#pragma unroll
        for (int j = 0; j < 8; j++) {
            int q = p + 4 * j;
            size_t g = (size_t)(rowBase + rrow) * 32 + q;
            float4 mv = ((const float4*)mean  )[g];
            float4 lv = ((const float4*)logvar)[g];
            float4 ev = ((const float4*)eps   )[g];
            float4 z4;
            z4.x = fmaf(ev.x, __expf(0.5f * lv.x), mv.x);
            z4.y = fmaf(ev.y, __expf(0.5f * lv.y), mv.y);
            z4.z = fmaf(ev.z, __expf(0.5f * lv.z), mv.z);
            z4.w = fmaf(ev.w, __expf(0.5f * lv.w), mv.w);
            part += lv.x + lv.y + lv.z + lv.w;
            part = fmaf(ev.x, ev.x, part);
            part = fmaf(ev.y, ev.y, part);
            part = fmaf(ev.z, ev.z, part);
            part = fmaf(ev.w, ev.w, part);
            if (q < 16)
                *(float4*)&sZ1[rrow * PZ + 4 * q] = z4;
            else
                *(float4*)&sZ2[rrow * PZ + 4 * (q - 16)] = z4;
        }
        part += __shfl_xor_sync(0xffffffffu, part, 1);
        part += __shfl_xor_sync(0xffffffffu, part, 2);
        if (p == 0) sQ0[rrow] = -0.5f * part;
    }

    float ldp[4] = {0.f, 0.f, 0.f, 0.f};
    float ssp[4] = {0.f, 0.f, 0.f, 0.f};

    // ================= couplings =================
#pragma unroll 1
    for (int cc = 0; cc < NC; cc++) {
        CP_WAIT1();
        __syncthreads();

        const float* sB0 = sm + OB + 192 * (cc & 1);
        const float* sB1 = sB0 + 64;
        const float* sB2 = sB0 + 128;
        const float* sZa = (cc & 1) ? sZ2 : sZ1;
        float*       sZu = (cc & 1) ? sZ1 : sZ2;

        // ---- GEMM1: H = tanh(Za @ W0^T + b0); m32 x n16 (wn3: n8) ----
        {
            const int NT = (wn < 3) ? 2 : 1;
            float acc[2][2][4] = {};
#pragma unroll
            for (int c = 0; c < 4; c++) {
                unsigned ah[2][4], al[2][4];
#pragma unroll
                for (int s2 = 0; s2 < 2; s2++) {
                    int ra0 = rb + 16 * s2 + gid, ra1 = ra0 + 8;
                    float2 v00 = ((const float2*)&sZa[ra0 * PZ])[tig +     8 * c];
                    float2 v10 = ((const float2*)&sZa[ra1 * PZ])[tig +     8 * c];
                    float2 v01 = ((const float2*)&sZa[ra0 * PZ])[tig + 4 + 8 * c];
                    float2 v11 = ((const float2*)&sZa[ra1 * PZ])[tig + 4 + 8 * c];
                    split2(v00.x, v00.y, ah[s2][0], al[s2][0]);
                    split2(v10.x, v10.y, ah[s2][1], al[s2][1]);
                    split2(v01.x, v01.y, ah[s2][2], al[s2][2]);
                    split2(v11.x, v11.y, ah[s2][3], al[s2][3]);
                }
                unsigned bh0[2], bh1[2], bl0[2], bl1[2];
                ldsm4(bh0[0], bh1[0], bh0[1], bh1[1], adrW0h + 32u * c);
                ldsm4(bl0[0], bl1[0], bl0[1], bl1[1], adrW0l + 32u * c);
                // product-major issue: hh for all accs, then hl, then lh
#pragma unroll
                for (int nn = 0; nn < 2; nn++) {
                    if (nn >= NT) break;
#pragma unroll
                    for (int s2 = 0; s2 < 2; s2++)
                        mma16(acc[s2][nn], ah[s2], bh0[nn], bh1[nn]);
                }
#pragma unroll
                for (int nn = 0; nn < 2; nn++) {
                    if (nn >= NT) break;
#pragma unroll
                    for (int s2 = 0; s2 < 2; s2++)
                        mma16(acc[s2][nn], ah[s2], bl0[nn], bl1[nn]);
                }
#pragma unroll
                for (int nn = 0; nn < 2; nn++) {
                    if (nn >= NT) break;
#pragma unroll
                    for (int s2 = 0; s2 < 2; s2++)
                        mma16(acc[s2][nn], al[s2], bh0[nn], bh1[nn]);
                }
            }
            // epilogue: bias + tanh, write H pre-split/packed
#pragma unroll
            for (int nn = 0; nn < 2; nn++) {
                if (nn >= NT) break;
                int nt  = 2 * wn + nn;
                int col = 8 * nt + 2 * tig;
                int kp  = 4 * nt + tig;
                float bb0 = sB0[col], bb1 = sB0[col + 1];
#pragma unroll
                for (int s2 = 0; s2 < 2; s2++) {
                    int ra0 = rb + 16 * s2 + gid, ra1 = ra0 + 8;
                    float t00 = tanh_fast(acc[s2][nn][0] + bb0);
                    float t01 = tanh_fast(acc[s2][nn][1] + bb1);
                    float t10 = tanh_fast(acc[s2][nn][2] + bb0);
                    float t11 = tanh_fast(acc[s2][nn][3] + bb1);
                    unsigned h, l;
                    split2(t00, t01, h, l);
                    uHH[ra0 * KPI + kp] = h;
                    uHL[ra0 * KPI + kp] = l;
                    split2(t10, t11, h, l);
                    uHH[ra1 * KPI + kp] = h;
                    uHL[ra1 * KPI + kp] = l;
                }
            }
        }
        CP_WAIT0();                    // W12(cc) landed
        __syncthreads();               // H visible; W0(cc) reads done

        // ---- prefetch {W0,b}(cc+1) (overlaps GEMM2; W0 buffer now free) ----
        if (cc < 3) {
            const float4* s0 = (const float4*)(&gW[cc + 1][0]);
            float4* d0 = (float4*)(sm + OW0);
            for (int i = tid; i < 4032 / 4; i += TPB) cp16(d0 + i, s0 + i);
            if (tid < 48)
                cp16((float4*)(sm + OB + 192 * ((cc + 1) & 1)) + tid,
                     (const float4*)(&gBB[cc + 1][0]) + tid);
            CP_COMMIT();
        }

        // ---- GEMM2: mu/sig heads; m32 x n16 (2 tiles), K=64 ----
        {
            float am [2][2][4] = {};
            float as2[2][2][4] = {};
#pragma unroll
            for (int c = 0; c < 4; c++) {
                unsigned ah[2][4], al[2][4];
                ldsm4(ah[0][0], ah[0][1], ah[0][2], ah[0][3], adrAh0 + 32u * c);
                ldsm4(al[0][0], al[0][1], al[0][2], al[0][3], adrAl0 + 32u * c);
                ldsm4(ah[1][0], ah[1][1], ah[1][2], ah[1][3], adrAh1 + 32u * c);
                ldsm4(al[1][0], al[1][1], al[1][2], al[1][3], adrAl1 + 32u * c);
                unsigned b1h0[2], b1h1[2], b1l0[2], b1l1[2];
                unsigned b2h0[2], b2h1[2], b2l0[2], b2l1[2];
                ldsm4(b1h0[0], b1h1[0], b1h0[1], b1h1[1], adrW1h + 32u * c);
                ldsm4(b1l0[0], b1l1[0], b1l0[1], b1l1[1], adrW1l + 32u * c);
                ldsm4(b2h0[0], b2h1[0], b2h0[1], b2h1[1], adrW2h + 32u * c);
                ldsm4(b2l0[0], b2l1[0], b2l0[1], b2l1[1], adrW2l + 32u * c);
                // product-major over all 8 accumulators
#pragma unroll
                for (int nn = 0; nn < 2; nn++)
#pragma unroll
                    for (int s2 = 0; s2 < 2; s2++)
                        mma16(am[s2][nn], ah[s2], b1h0[nn], b1h1[nn]);
#pragma unroll
                for (int nn = 0; nn < 2; nn++)
#pragma unroll
                    for (int s2 = 0; s2 < 2; s2++)
                        mma16(as2[s2][nn], ah[s2], b2h0[nn], b2h1[nn]);
#pragma unroll
                for (int nn = 0; nn < 2; nn++)
#pragma unroll
                    for (int s2 = 0; s2 < 2; s2++)
                        mma16(am[s2][nn], ah[s2], b1l0[nn], b1l1[nn]);
#pragma unroll
                for (int nn = 0; nn < 2; nn++)
#pragma unroll
                    for (int s2 = 0; s2 < 2; s2++)
                        mma16(as2[s2][nn], ah[s2], b2l0[nn], b2l1[nn]);
#pragma unroll
                for (int nn = 0; nn < 2; nn++)
#pragma unroll
                    for (int s2 = 0; s2 < 2; s2++)
                        mma16(am[s2][nn], al[s2], b1h0[nn], b1h1[nn]);
#pragma unroll
                for (int nn = 0; nn < 2; nn++)
#pragma unroll
                    for (int s2 = 0; s2 < 2; s2++)
                        mma16(as2[s2][nn], al[s2], b2h0[nn], b2h1[nn]);
            }
            // ---- epilogue: sig, z update, logdet (float2 z access) ----
            const bool fin = (cc >= 2);
#pragma unroll
            for (int s2 = 0; s2 < 2; s2++) {
                int ra0 = rb + 16 * s2 + gid, ra1 = ra0 + 8;
#pragma unroll
                for (int nn = 0; nn < 2; nn++) {
                    int col = 8 * (2 * wn + nn) + 2 * tig;
                    float2 bm2 = *(const float2*)&sB1[col];
                    float2 bs2 = *(const float2*)&sB2[col];
                    float2 z0 = *(const float2*)&sZu[ra0 * PZ + col];
                    float2 z1 = *(const float2*)&sZu[ra1 * PZ + col];
                    {
                        float mu = am[s2][nn][0] + bm2.x;
                        float x  = as2[s2][nn][0] + bs2.x;
                        float sg = fmaf(tanh_fast(0.5f * x), 0.5f, 0.5f);
                        ldp[2 * s2] += __logf(sg);
                        z0.x = fmaf(z0.x, sg, mu);
                        if (fin) ssp[2 * s2] = fmaf(z0.x, z0.x, ssp[2 * s2]);
                    }
                    {
                        float mu = am[s2][nn][1] + bm2.y;
                        float x  = as2[s2][nn][1] + bs2.y;
                        float sg = fmaf(tanh_fast(0.5f * x), 0.5f, 0.5f);
                        ldp[2 * s2] += __logf(sg);
                        z0.y = fmaf(z0.y, sg, mu);
                        if (fin) ssp[2 * s2] = fmaf(z0.y, z0.y, ssp[2 * s2]);
                    }
                    {
                        float mu = am[s2][nn][2] + bm2.x;
                        float x  = as2[s2][nn][2] + bs2.x;
                        float sg = fmaf(tanh_fast(0.5f * x), 0.5f, 0.5f);
                        ldp[2 * s2 + 1] += __logf(sg);
                        z1.x = fmaf(z1.x, sg, mu);
                        if (fin) ssp[2 * s2 + 1] = fmaf(z1.x, z1.x, ssp[2 * s2 + 1]);
                    }
                    {
                        float mu = am[s2][nn][3] + bm2.y;
                        float x  = as2[s2][nn][3] + bs2.y;
                        float sg = fmaf(tanh_fast(0.5f * x), 0.5f, 0.5f);
                        ldp[2 * s2 + 1] += __logf(sg);
                        z1.y = fmaf(z1.y, sg, mu);
                        if (fin) ssp[2 * s2 + 1] = fmaf(z1.y, z1.y, ssp[2 * s2 + 1]);
                    }
                    *(float2*)&sZu[ra0 * PZ + col] = z0;
                    *(float2*)&sZu[ra1 * PZ + col] = z1;
                }
            }
        }
        __syncthreads();               // z updated; W12(cc) reads done

        // ---- prefetch {W12}(cc+1) (overlaps next GEMM1) ----
        if (cc < 3) {
            const float4* s1 = (const float4*)(&gW[cc + 1][GW12]);
            float4* d1 = (float4*)(sm + OW12);
            for (int i = tid; i < 9216 / 4; i += TPB) cp16(d1 + i, s1 + i);
            CP_COMMIT();
        }
    }

    // ================= write z (coalesced float4) =================
#pragma unroll
    for (int i = 0; i < 8; i++) {
        int idx = tid + TPB * i;            // 0..2047
        int row = idx >> 5, q = idx & 31;
        float4 v = (q < 16)
            ? *(const float4*)&sZ1[row * PZ + 4 * q]
            : *(const float4*)&sZ2[row * PZ + 4 * (q - 16)];
        ((float4*)out)[(size_t)(rowBase + row) * 32 + q] = v;
    }

    // ================= densities =================
#pragma unroll
    for (int s = 0; s < 4; s++) {
        float l = ldp[s], v = ssp[s];
        l += __shfl_xor_sync(0xffffffffu, l, 1);
        l += __shfl_xor_sync(0xffffffffu, l, 2);
        v += __shfl_xor_sync(0xffffffffu, v, 1);
        v += __shfl_xor_sync(0xffffffffu, v, 2);
        if (tig == 0) {
            int row = rb + 16 * (s >> 1) + 8 * (s & 1) + gid;
            sLD[wn * 64 + row] = l;
            sSS[wn * 64 + row] = v;
        }
    }
    __syncthreads();
    if (tid < 64) {
        float l = sLD[tid] + sLD[64 + tid] + sLD[128 + tid] + sLD[192 + tid];
        float s = sSS[tid] + sSS[64 + tid] + sSS[128 + tid] + sSS[192 + tid];
        size_t base = (size_t)Brows * ZZ;
        out[base + rowBase + tid]         = -0.5f * s;
        out[base + Brows + rowBase + tid] = sQ0[tid] - l;
    }
}

extern "C" void kernel_launch(void* const* d_in, const int* in_sizes, int n_in,
                              void* d_out, int out_size)
{
    const float* mean   = (const float*)d_in[0];
    const float* logvar = (const float*)d_in[1];
    const float* eps    = (const float*)d_in[2];
    const float* W_in   = (const float*)d_in[3];
    const float* b_in   = (const float*)d_in[4];
    const float* W_mu   = (const float*)d_in[5];
    const float* b_mu   = (const float*)d_in[6];
    const float* W_sig  = (const float*)d_in[7];
    const float* b_sig  = (const float*)d_in[8];
    float* out = (float*)d_out;

    int Brows = in_sizes[0] / ZZ;

    cudaFuncSetAttribute(flow_kernel, cudaFuncAttributeMaxDynamicSharedMemorySize, SMEM_BYTES);

    presplit_kernel<<<NC, 256>>>(W_in, b_in, W_mu, b_mu, W_sig, b_sig);
    flow_kernel<<<Brows / MR, TPB, SMEM_BYTES>>>(mean, logvar, eps, out, Brows);
}